// round 13
// baseline (speedup 1.0000x reference)
#include <cuda_runtime.h>
#include <cuda.h>
#include <cuda_fp16.h>
#include <cstdint>

// ============================================================================
// out[m,n] = sum_k A[m,k] * (q[n,k]-zeros[n,k/128])*scales[n,k/128] + bias[n]
// M=2048, K=4096, N=4096, G=32.
// R13: SINGLE fused kernel. CTAs 0..147 stream-dequant A->fp16 / W->fp16 in
// 32 K-chunks of 128 cols (chunk == quant group), publishing per-chunk flags;
// all 592 CTAs run the R12 GEMM (128x64 tile, 4 warps, 4 CTAs/SM) off a
// persistent tile queue, gating each TMA on its chunk flag.
// Evidence: R12 GEMM ~at its 86.5% slot ceiling (tensor-busy 114us invariant);
// the 23us serialized pass-1 is the last big addressable term -> overlap it.
// ============================================================================

static constexpr int Mdim = 2048, Kdim = 4096, Ndim = 4096, Gdim = 32;

static constexpr int TILE_M = 128, TILE_N = 64, TILE_K = 64;
static constexpr int STAGES = 2;
static constexpr int A_STAGE_BYTES = TILE_M * TILE_K * 2;  // 16384
static constexpr int B_STAGE_BYTES = TILE_N * TILE_K * 2;  // 8192
static constexpr int STAGE_BYTES = A_STAGE_BYTES + B_STAGE_BYTES;  // 24576
static constexpr int OFF_FULL  = 0;    // 2 x 8B
static constexpr int OFF_TILE  = 16;   // 4B broadcast slot
static constexpr int OFF_STAGE = 1024;
static constexpr int SMEM_TOTAL = OFF_STAGE + STAGES * STAGE_BYTES;  // 50176
static constexpr int NUM_SLABS = Kdim / TILE_K;   // 64
static constexpr int TILES_N = Ndim / TILE_N;     // 64
static constexpr int NUM_TILES = (Mdim / TILE_M) * TILES_N;  // 1024
static constexpr int GRID_GEMM = 592;             // 4/SM x 148

// dequant streaming
static constexpr int NDQ = 148;                   // producer CTAs (1/SM)
static constexpr int NCHUNKS = 32;                // K-chunks of 128 (== group)
static constexpr int UNITS_A = (Mdim * 128) / 8;  // 32768 uint4 per chunk
static constexpr int UNITS_W = (Ndim * 128) / 8;  // 65536
static constexpr int UNITS   = UNITS_A + UNITS_W; // 98304
static constexpr int DQ_STRIDE = NDQ * 128;       // 18944

static __device__ __align__(1024) __half g_A16[(size_t)Mdim * Kdim];
static __device__ __align__(1024) __half g_W16[(size_t)Ndim * Kdim];
// [0] = tile queue counter, [1..32] = per-chunk done counters
static __device__ unsigned g_ctrl[1 + NCHUNKS];

#define DEVINL __device__ __forceinline__

DEVINL uint32_t smem_u32(const void* p) {
    uint32_t a;
    asm("{ .reg .u64 t; cvta.to.shared.u64 t, %1; cvt.u32.u64 %0, t; }"
        : "=r"(a) : "l"(p));
    return a;
}
DEVINL void mbar_init(uint32_t a, uint32_t cnt) {
    asm volatile("mbarrier.init.shared.b64 [%0], %1;" :: "r"(a), "r"(cnt) : "memory");
}
DEVINL void mbar_expect_tx(uint32_t a, uint32_t bytes) {
    asm volatile("mbarrier.arrive.expect_tx.shared.b64 _, [%0], %1;"
                 :: "r"(a), "r"(bytes) : "memory");
}
DEVINL void mbar_wait(uint32_t a, uint32_t parity) {
    asm volatile(
        "{\n\t.reg .pred P;\n\t"
        "LAB_%=:\n\t"
        "mbarrier.try_wait.parity.acquire.cta.shared::cta.b64 P, [%0], %1, 0x989680;\n\t"
        "@!P bra LAB_%=;\n\t"
        "}" :: "r"(a), "r"(parity) : "memory");
}
DEVINL void tma_2d(uint32_t smem, const void* map, int x, int y, uint32_t bar) {
    asm volatile(
        "cp.async.bulk.tensor.2d.shared::cta.global.tile.mbarrier::complete_tx::bytes "
        "[%0], [%1, {%2, %3}], [%4];"
        :: "r"(smem), "l"(map), "r"(x), "r"(y), "r"(bar) : "memory");
}
DEVINL void fence_proxy_async() {
    asm volatile("fence.proxy.async.shared::cta;" ::: "memory");
}
DEVINL void ldsm_x4(uint32_t& r0, uint32_t& r1, uint32_t& r2, uint32_t& r3,
                    uint32_t addr) {
    asm volatile("ldmatrix.sync.aligned.m8n8.x4.shared.b16 {%0,%1,%2,%3}, [%4];"
                 : "=r"(r0), "=r"(r1), "=r"(r2), "=r"(r3) : "r"(addr));
}
DEVINL void mma16816(float* c, const uint32_t* a, uint32_t b0, uint32_t b1) {
    asm volatile(
        "mma.sync.aligned.m16n8k16.row.col.f32.f16.f16.f32 "
        "{%0,%1,%2,%3}, {%4,%5,%6,%7}, {%8,%9}, {%0,%1,%2,%3};"
        : "+f"(c[0]), "+f"(c[1]), "+f"(c[2]), "+f"(c[3])
        : "r"(a[0]), "r"(a[1]), "r"(a[2]), "r"(a[3]), "r"(b0), "r"(b1));
}
// consumer-side: spin until chunk c fully published (acquire)
DEVINL void wait_chunk(int c) {
    unsigned v;
    do {
        asm volatile("ld.acquire.gpu.global.u32 %0, [%1];"
                     : "=r"(v) : "l"(g_ctrl + 1 + c) : "memory");
    } while (v < (unsigned)NDQ);
}

// ---------------------------- fused kernel ----------------------------------
__global__ void __launch_bounds__(128, 4)
fused_kernel(const __grid_constant__ CUtensorMap tmA,
             const __grid_constant__ CUtensorMap tmB,
             const float* __restrict__ A, const int* __restrict__ q,
             const float* __restrict__ scales, const float* __restrict__ zeros,
             const float* __restrict__ bias,
             __half* __restrict__ A16, __half* __restrict__ W16,
             float* __restrict__ out) {
    extern __shared__ char smem[];
    uint32_t sb = smem_u32(smem);
    int tid = threadIdx.x, wid = tid >> 5, lane = tid & 31;
    int wm = wid >> 1, wn = wid & 1;  // warp coords: 2(M) x 2(N)

    if (tid == 0) {
        #pragma unroll
        for (int i = 0; i < STAGES; i++) mbar_init(sb + OFF_FULL + i * 8, 1);
        fence_proxy_async();
    }
    __syncthreads();

    // ---------------- producer phase: CTAs 0..NDQ-1 stream-dequant ----------
    if (blockIdx.x < NDQ) {
        int base = blockIdx.x * 128 + tid;
        for (int c = 0; c < NCHUNKS; c++) {
            int k0 = c * 128;
            #pragma unroll
            for (int it = 0; it < 6; it++) {      // 6*18944 >= 98304
                int u = base + it * DQ_STRIDE;
                if (u < UNITS) {
                    if (u < UNITS_A) {            // A fp32 -> fp16
                        int row = u >> 4, cb = u & 15;
                        const float4* src = reinterpret_cast<const float4*>(
                            A + (size_t)row * Kdim + k0 + cb * 8);
                        float4 x = src[0], y = src[1];
                        __half2 h[4];
                        h[0] = __floats2half2_rn(x.x, x.y);
                        h[1] = __floats2half2_rn(x.z, x.w);
                        h[2] = __floats2half2_rn(y.x, y.y);
                        h[3] = __floats2half2_rn(y.z, y.w);
                        *reinterpret_cast<uint4*>(
                            A16 + (size_t)row * Kdim + k0 + cb * 8) =
                            *reinterpret_cast<uint4*>(h);
                    } else {                      // W dequant int32 -> fp16
                        int v = u - UNITS_A;
                        int row = v >> 4, cb = v & 15;
                        float s = scales[row * Gdim + c];  // chunk == group
                        float z = zeros[row * Gdim + c];
                        const int4* src = reinterpret_cast<const int4*>(
                            q + (size_t)row * Kdim + k0 + cb * 8);
                        int4 a = src[0], b = src[1];
                        __half2 h[4];
                        h[0] = __floats2half2_rn(((float)a.x - z) * s,
                                                 ((float)a.y - z) * s);
                        h[1] = __floats2half2_rn(((float)a.z - z) * s,
                                                 ((float)a.w - z) * s);
                        h[2] = __floats2half2_rn(((float)b.x - z) * s,
                                                 ((float)b.y - z) * s);
                        h[3] = __floats2half2_rn(((float)b.z - z) * s,
                                                 ((float)b.w - z) * s);
                        *reinterpret_cast<uint4*>(
                            W16 + (size_t)row * Kdim + k0 + cb * 8) =
                            *reinterpret_cast<uint4*>(h);
                    }
                }
            }
            __syncthreads();                      // CTA's slice of chunk done
            if (tid == 0) {
                __threadfence();                  // publish writes (release)
                atomicAdd(&g_ctrl[1 + c], 1u);
            }
        }
    }

    // ---------------- GEMM: persistent tile queue ---------------------------
    // ldmatrix address components (SW128: xor = (lane&7)*16)
    int a_row = wm * 64 + (lane & 15);
    int a_khalf = (lane & 16);
    int b_row = wn * 32 + ((lane & 16) >> 1) + (lane & 7);
    int b_khalf = (lane & 8) << 1;
    int sw_xor = (lane & 7) * 16;

    uint32_t aRowOff[4], bRowOff[2];
    #pragma unroll
    for (int mb = 0; mb < 4; mb++) aRowOff[mb] = (uint32_t)(a_row + mb * 16) * 128;
    #pragma unroll
    for (int j = 0; j < 2; j++)
        bRowOff[j] = A_STAGE_BYTES + (uint32_t)(b_row + j * 16) * 128;

    unsigned* tileSlot = reinterpret_cast<unsigned*>(smem + OFF_TILE);
    int gr = lane >> 2, gc = (lane & 3) * 2;

    for (;;) {
        __syncthreads();   // prior tile's smem reads done; tileSlot reusable
        if (tid == 0) *tileSlot = atomicAdd(&g_ctrl[0], 1u);
        __syncthreads();
        unsigned t = *tileSlot;
        if (t >= NUM_TILES) break;
        int bm = t >> 6, bn = t & (TILES_N - 1);

        if (tid == 0) {
            wait_chunk(0);                        // covers slabs 0 and 1
            #pragma unroll
            for (int j = 0; j < STAGES; j++) {
                uint32_t fullb = sb + OFF_FULL + j * 8;
                uint32_t sA = sb + OFF_STAGE + j * STAGE_BYTES;
                mbar_expect_tx(fullb, STAGE_BYTES);
                tma_2d(sA, &tmA, j * TILE_K, bm * TILE_M, fullb);
                tma_2d(sA + A_STAGE_BYTES, &tmB, j * TILE_K, bn * TILE_N, fullb);
            }
        }

        float acc[4][4][4];
        #pragma unroll
        for (int mb = 0; mb < 4; mb++)
            #pragma unroll
            for (int nb = 0; nb < 4; nb++)
                #pragma unroll
                for (int i = 0; i < 4; i++) acc[mb][nb][i] = 0.0f;

        for (int s = 0; s < NUM_SLABS; s++) {
            int st = s & 1;
            int ph = (s >> 1) & 1;
            mbar_wait(sb + OFF_FULL + st * 8, ph);
            uint32_t base = sb + OFF_STAGE + st * STAGE_BYTES;

            #pragma unroll
            for (int ks = 0; ks < 4; ks++) {
                int koffA = ((ks * 32) | a_khalf) ^ sw_xor;
                int koffB = ((ks * 32) | b_khalf) ^ sw_xor;
                uint32_t a[4][4], b[2][4];
                #pragma unroll
                for (int mb = 0; mb < 4; mb++)
                    ldsm_x4(a[mb][0], a[mb][1], a[mb][2], a[mb][3],
                            base + aRowOff[mb] + koffA);
                #pragma unroll
                for (int j = 0; j < 2; j++)
                    ldsm_x4(b[j][0], b[j][1], b[j][2], b[j][3],
                            base + bRowOff[j] + koffB);
                #pragma unroll
                for (int mb = 0; mb < 4; mb++) {
                    #pragma unroll
                    for (int nb = 0; nb < 4; nb++) {
                        int j = nb >> 1, h = (nb & 1) * 2;
                        mma16816(acc[mb][nb], a[mb], b[j][h], b[j][h + 1]);
                    }
                }
            }

            __syncthreads();                      // stage st consumed
            if (tid == 0 && s + STAGES < NUM_SLABS) {
                wait_chunk((s + STAGES) >> 1);
                uint32_t fullb = sb + OFF_FULL + st * 8;
                mbar_expect_tx(fullb, STAGE_BYTES);
                tma_2d(base, &tmA, (s + STAGES) * TILE_K, bm * TILE_M, fullb);
                tma_2d(base + A_STAGE_BYTES, &tmB, (s + STAGES) * TILE_K,
                       bn * TILE_N, fullb);
            }
        }

        // ---------------- epilogue ----------------
        #pragma unroll
        for (int mb = 0; mb < 4; mb++) {
            int row = bm * TILE_M + wm * 64 + mb * 16 + gr;
            float* orow0 = out + (size_t)row * Ndim;
            float* orow1 = out + (size_t)(row + 8) * Ndim;
            #pragma unroll
            for (int nb = 0; nb < 4; nb++) {
                int col = bn * TILE_N + wn * 32 + nb * 8 + gc;
                float2 bv = __ldg(reinterpret_cast<const float2*>(bias + col));
                float2 v0 = {acc[mb][nb][0] + bv.x, acc[mb][nb][1] + bv.y};
                float2 v1 = {acc[mb][nb][2] + bv.x, acc[mb][nb][3] + bv.y};
                *reinterpret_cast<float2*>(orow0 + col) = v0;
                *reinterpret_cast<float2*>(orow1 + col) = v1;
            }
        }
    }
}

// ---------------------------- host launch -----------------------------------
typedef CUresult (*PFN_encodeTiled)(
    CUtensorMap*, CUtensorMapDataType, cuuint32_t, void*,
    const cuuint64_t*, const cuuint64_t*, const cuuint32_t*, const cuuint32_t*,
    CUtensorMapInterleave, CUtensorMapSwizzle, CUtensorMapL2promotion,
    CUtensorMapFloatOOBfill);

extern "C" void kernel_launch(void* const* d_in, const int* in_sizes, int n_in,
                              void* d_out, int out_size) {
    const float* A      = (const float*)d_in[0];
    const int*   qw     = (const int*)  d_in[1];
    const float* scales = (const float*)d_in[2];
    const float* zeros  = (const float*)d_in[3];
    const float* bias   = (const float*)d_in[4];
    float*       out    = (float*)d_out;

    void *pA16 = nullptr, *pW16 = nullptr, *pCtrl = nullptr;
    cudaGetSymbolAddress(&pA16, g_A16);
    cudaGetSymbolAddress(&pW16, g_W16);
    cudaGetSymbolAddress(&pCtrl, g_ctrl);
    __half* A16 = (__half*)pA16;
    __half* W16 = (__half*)pW16;

    // reset tile queue + chunk flags (graph-capturable async memset, stream 0)
    cudaMemsetAsync(pCtrl, 0, sizeof(unsigned) * (1 + NCHUNKS));

    PFN_encodeTiled enc = nullptr;
    cudaDriverEntryPointQueryResult qres;
    cudaGetDriverEntryPointByVersion("cuTensorMapEncodeTiled", (void**)&enc,
                                     12000, cudaEnableDefault, &qres);
    if (!enc) return;

    CUtensorMap tmA, tmB;
    {
        cuuint64_t dims[2]    = {(cuuint64_t)Kdim, (cuuint64_t)Mdim};
        cuuint64_t strides[1] = {(cuuint64_t)Kdim * 2};
        cuuint32_t box[2]     = {TILE_K, TILE_M};  // {64, 128}
        cuuint32_t es[2]      = {1, 1};
        enc(&tmA, CU_TENSOR_MAP_DATA_TYPE_FLOAT16, 2, A16, dims, strides, box, es,
            CU_TENSOR_MAP_INTERLEAVE_NONE, CU_TENSOR_MAP_SWIZZLE_128B,
            CU_TENSOR_MAP_L2_PROMOTION_L2_128B, CU_TENSOR_MAP_FLOAT_OOB_FILL_NONE);
    }
    {
        cuuint64_t dims[2]    = {(cuuint64_t)Kdim, (cuuint64_t)Ndim};
        cuuint64_t strides[1] = {(cuuint64_t)Kdim * 2};
        cuuint32_t box[2]     = {TILE_K, TILE_N};  // {64, 64}
        cuuint32_t es[2]      = {1, 1};
        enc(&tmB, CU_TENSOR_MAP_DATA_TYPE_FLOAT16, 2, W16, dims, strides, box, es,
            CU_TENSOR_MAP_INTERLEAVE_NONE, CU_TENSOR_MAP_SWIZZLE_128B,
            CU_TENSOR_MAP_L2_PROMOTION_L2_128B, CU_TENSOR_MAP_FLOAT_OOB_FILL_NONE);
    }

    cudaFuncSetAttribute(fused_kernel,
                         cudaFuncAttributeMaxDynamicSharedMemorySize, SMEM_TOTAL);
    fused_kernel<<<GRID_GEMM, 128, SMEM_TOTAL>>>(
        tmA, tmB, A, qw, scales, zeros, bias, A16, W16, out);
}

// round 14
// speedup vs baseline: 1.7311x; 1.7311x over previous
#include <cuda_runtime.h>
#include <cuda.h>
#include <cuda_fp16.h>
#include <cstdint>

// ============================================================================
// out[m,n] = sum_k A[m,k] * (q[n,k]-zeros[n,k/128])*scales[n,k/128] + bias[n]
// M=2048, K=4096, N=4096, G=32.
// R14 = R12 (best, 162.3us) + pass-1 MLP bump (32 elems/thread, 8 LDG.128).
// R13's CTA-level fusion starved both phases (tensor 59%) -> reverted.
// GEMM: fp16 mma.sync.m16n8k16, TILE 128x64, 128 thr / 4 warps (2x2),
// warp tile 64x32, 4 CTAs/SM, 2-stage TMA, static (64,16) grid.
// ============================================================================

static constexpr int Mdim = 2048, Kdim = 4096, Ndim = 4096, Gdim = 32;

static constexpr int TILE_M = 128, TILE_N = 64, TILE_K = 64;
static constexpr int STAGES = 2;
static constexpr int A_STAGE_BYTES = TILE_M * TILE_K * 2;  // 16384
static constexpr int B_STAGE_BYTES = TILE_N * TILE_K * 2;  // 8192
static constexpr int STAGE_BYTES = A_STAGE_BYTES + B_STAGE_BYTES;  // 24576
static constexpr int OFF_FULL  = 0;    // 2 x 8B
static constexpr int OFF_STAGE = 1024; // 1024-aligned for SW128
static constexpr int SMEM_TOTAL = OFF_STAGE + STAGES * STAGE_BYTES;  // 50176
static constexpr int NUM_SLABS = Kdim / TILE_K;  // 64

static __device__ __align__(1024) __half g_A16[(size_t)Mdim * Kdim];
static __device__ __align__(1024) __half g_W16[(size_t)Ndim * Kdim];

#define DEVINL __device__ __forceinline__

DEVINL uint32_t smem_u32(const void* p) {
    uint32_t a;
    asm("{ .reg .u64 t; cvta.to.shared.u64 t, %1; cvt.u32.u64 %0, t; }"
        : "=r"(a) : "l"(p));
    return a;
}
DEVINL void mbar_init(uint32_t a, uint32_t cnt) {
    asm volatile("mbarrier.init.shared.b64 [%0], %1;" :: "r"(a), "r"(cnt) : "memory");
}
DEVINL void mbar_expect_tx(uint32_t a, uint32_t bytes) {
    asm volatile("mbarrier.arrive.expect_tx.shared.b64 _, [%0], %1;"
                 :: "r"(a), "r"(bytes) : "memory");
}
DEVINL void mbar_wait(uint32_t a, uint32_t parity) {
    asm volatile(
        "{\n\t.reg .pred P;\n\t"
        "LAB_%=:\n\t"
        "mbarrier.try_wait.parity.acquire.cta.shared::cta.b64 P, [%0], %1, 0x989680;\n\t"
        "@!P bra LAB_%=;\n\t"
        "}" :: "r"(a), "r"(parity) : "memory");
}
DEVINL void tma_2d(uint32_t smem, const void* map, int x, int y, uint32_t bar) {
    asm volatile(
        "cp.async.bulk.tensor.2d.shared::cta.global.tile.mbarrier::complete_tx::bytes "
        "[%0], [%1, {%2, %3}], [%4];"
        :: "r"(smem), "l"(map), "r"(x), "r"(y), "r"(bar) : "memory");
}
DEVINL void fence_proxy_async() {
    asm volatile("fence.proxy.async.shared::cta;" ::: "memory");
}
DEVINL void ldsm_x4(uint32_t& r0, uint32_t& r1, uint32_t& r2, uint32_t& r3,
                    uint32_t addr) {
    asm volatile("ldmatrix.sync.aligned.m8n8.x4.shared.b16 {%0,%1,%2,%3}, [%4];"
                 : "=r"(r0), "=r"(r1), "=r"(r2), "=r"(r3) : "r"(addr));
}
DEVINL void mma16816(float* c, const uint32_t* a, uint32_t b0, uint32_t b1) {
    asm volatile(
        "mma.sync.aligned.m16n8k16.row.col.f32.f16.f16.f32 "
        "{%0,%1,%2,%3}, {%4,%5,%6,%7}, {%8,%9}, {%0,%1,%2,%3};"
        : "+f"(c[0]), "+f"(c[1]), "+f"(c[2]), "+f"(c[3])
        : "r"(a[0]), "r"(a[1]), "r"(a[2]), "r"(a[3]), "r"(b0), "r"(b1));
}

// ---------------------------- Pass 1: fused, 32 elems/thread ----------------
static constexpr int NBLK_A = (Mdim * Kdim / 32) / 256;  // 1024
static constexpr int NBLK_W = (Ndim * Kdim / 32) / 256;  // 2048

__global__ void __launch_bounds__(256) pass1_kernel(
    const float* __restrict__ A, const int* __restrict__ q,
    const float* __restrict__ sc, const float* __restrict__ zr,
    __half* __restrict__ A16, __half* __restrict__ W16) {
    int bid = blockIdx.x;
    if (bid < NBLK_A) {
        int t = bid * 256 + threadIdx.x;
        const float4* a4 = reinterpret_cast<const float4*>(A) + (size_t)t * 8;
        float4 v[8];
        #pragma unroll
        for (int i = 0; i < 8; i++) v[i] = a4[i];  // 8 LDG.128 in flight
        #pragma unroll
        for (int i = 0; i < 8; i += 2) {
            __half2 h[4];
            h[0] = __floats2half2_rn(v[i].x, v[i].y);
            h[1] = __floats2half2_rn(v[i].z, v[i].w);
            h[2] = __floats2half2_rn(v[i + 1].x, v[i + 1].y);
            h[3] = __floats2half2_rn(v[i + 1].z, v[i + 1].w);
            reinterpret_cast<uint4*>(A16)[(size_t)t * 4 + (i >> 1)] =
                *reinterpret_cast<uint4*>(h);
        }
    } else {
        int t = (bid - NBLK_A) * 256 + threadIdx.x;
        int k32 = t & (Kdim / 32 - 1);   // 128 chunks of 32 per row
        int n = t >> 7;
        int g = k32 >> 2;                // 4 chunks of 32 per group of 128
        float s = sc[n * Gdim + g];
        float z = zr[n * Gdim + g];
        const int4* qp = reinterpret_cast<const int4*>(q) + (size_t)t * 8;
        int4 v[8];
        #pragma unroll
        for (int i = 0; i < 8; i++) v[i] = qp[i];  // 8 LDG.128 in flight
        #pragma unroll
        for (int i = 0; i < 8; i += 2) {
            __half2 h[4];
            h[0] = __floats2half2_rn(((float)v[i].x - z) * s, ((float)v[i].y - z) * s);
            h[1] = __floats2half2_rn(((float)v[i].z - z) * s, ((float)v[i].w - z) * s);
            h[2] = __floats2half2_rn(((float)v[i+1].x - z) * s, ((float)v[i+1].y - z) * s);
            h[3] = __floats2half2_rn(((float)v[i+1].z - z) * s, ((float)v[i+1].w - z) * s);
            reinterpret_cast<uint4*>(W16)[(size_t)t * 4 + (i >> 1)] =
                *reinterpret_cast<uint4*>(h);
        }
    }
}

// ---------------------------- Pass 2: GEMM (R12, unchanged) -----------------
__global__ void __launch_bounds__(128, 4)
gemm_f16_kernel(const __grid_constant__ CUtensorMap tmA,
                const __grid_constant__ CUtensorMap tmB,
                const float* __restrict__ bias,
                float* __restrict__ out) {
    extern __shared__ char smem[];
    uint32_t sb = smem_u32(smem);
    int tid = threadIdx.x, wid = tid >> 5, lane = tid & 31;
    int bn = blockIdx.x, bm = blockIdx.y;
    int wm = wid >> 1, wn = wid & 1;  // warp coords: 2(M) x 2(N)

    if (tid == 0) {
        #pragma unroll
        for (int i = 0; i < STAGES; i++) mbar_init(sb + OFF_FULL + i * 8, 1);
        fence_proxy_async();
    }
    __syncthreads();

    // Prologue: fill both stages
    if (tid == 0) {
        #pragma unroll
        for (int j = 0; j < STAGES; j++) {
            uint32_t fullb = sb + OFF_FULL + j * 8;
            uint32_t sA = sb + OFF_STAGE + j * STAGE_BYTES;
            mbar_expect_tx(fullb, STAGE_BYTES);
            tma_2d(sA, &tmA, j * TILE_K, bm * TILE_M, fullb);
            tma_2d(sA + A_STAGE_BYTES, &tmB, j * TILE_K, bn * TILE_N, fullb);
        }
    }

    // ldmatrix address components (SW128: xor = (lane&7)*16)
    int a_row = wm * 64 + (lane & 15);                      // + mb*16, <=127
    int a_khalf = (lane & 16);
    int b_row = wn * 32 + ((lane & 16) >> 1) + (lane & 7);  // + j*16, <=63
    int b_khalf = (lane & 8) << 1;
    int sw_xor = (lane & 7) * 16;

    uint32_t aRowOff[4], bRowOff[2];
    #pragma unroll
    for (int mb = 0; mb < 4; mb++) aRowOff[mb] = (uint32_t)(a_row + mb * 16) * 128;
    #pragma unroll
    for (int j = 0; j < 2; j++)
        bRowOff[j] = A_STAGE_BYTES + (uint32_t)(b_row + j * 16) * 128;

    float acc[4][4][4];
    #pragma unroll
    for (int mb = 0; mb < 4; mb++)
        #pragma unroll
        for (int nb = 0; nb < 4; nb++)
            #pragma unroll
            for (int i = 0; i < 4; i++) acc[mb][nb][i] = 0.0f;

    for (int s = 0; s < NUM_SLABS; s++) {
        int st = s & 1;
        int ph = (s >> 1) & 1;
        mbar_wait(sb + OFF_FULL + st * 8, ph);
        uint32_t base = sb + OFF_STAGE + st * STAGE_BYTES;

        #pragma unroll
        for (int ks = 0; ks < 4; ks++) {
            int koffA = ((ks * 32) | a_khalf) ^ sw_xor;
            int koffB = ((ks * 32) | b_khalf) ^ sw_xor;
            uint32_t a[4][4], b[2][4];
            #pragma unroll
            for (int mb = 0; mb < 4; mb++)
                ldsm_x4(a[mb][0], a[mb][1], a[mb][2], a[mb][3],
                        base + aRowOff[mb] + koffA);
            #pragma unroll
            for (int j = 0; j < 2; j++)
                ldsm_x4(b[j][0], b[j][1], b[j][2], b[j][3],
                        base + bRowOff[j] + koffB);
            #pragma unroll
            for (int mb = 0; mb < 4; mb++) {
                #pragma unroll
                for (int nb = 0; nb < 4; nb++) {
                    int j = nb >> 1, h = (nb & 1) * 2;
                    mma16816(acc[mb][nb], a[mb], b[j][h], b[j][h + 1]);
                }
            }
        }

        // stage fully consumed -> one barrier, tid0 refills for slab s+2
        __syncthreads();
        if (tid == 0 && s + STAGES < NUM_SLABS) {
            uint32_t fullb = sb + OFF_FULL + st * 8;
            mbar_expect_tx(fullb, STAGE_BYTES);
            tma_2d(base, &tmA, (s + STAGES) * TILE_K, bm * TILE_M, fullb);
            tma_2d(base + A_STAGE_BYTES, &tmB, (s + STAGES) * TILE_K,
                   bn * TILE_N, fullb);
        }
    }

    // ---------------- epilogue ----------------
    int gr = lane >> 2, gc = (lane & 3) * 2;
    #pragma unroll
    for (int mb = 0; mb < 4; mb++) {
        int row = bm * TILE_M + wm * 64 + mb * 16 + gr;
        float* orow0 = out + (size_t)row * Ndim;
        float* orow1 = out + (size_t)(row + 8) * Ndim;
        #pragma unroll
        for (int nb = 0; nb < 4; nb++) {
            int col = bn * TILE_N + wn * 32 + nb * 8 + gc;
            float2 bv = __ldg(reinterpret_cast<const float2*>(bias + col));
            float2 v0 = {acc[mb][nb][0] + bv.x, acc[mb][nb][1] + bv.y};
            float2 v1 = {acc[mb][nb][2] + bv.x, acc[mb][nb][3] + bv.y};
            *reinterpret_cast<float2*>(orow0 + col) = v0;
            *reinterpret_cast<float2*>(orow1 + col) = v1;
        }
    }
}

// ---------------------------- host launch -----------------------------------
typedef CUresult (*PFN_encodeTiled)(
    CUtensorMap*, CUtensorMapDataType, cuuint32_t, void*,
    const cuuint64_t*, const cuuint64_t*, const cuuint32_t*, const cuuint32_t*,
    CUtensorMapInterleave, CUtensorMapSwizzle, CUtensorMapL2promotion,
    CUtensorMapFloatOOBfill);

extern "C" void kernel_launch(void* const* d_in, const int* in_sizes, int n_in,
                              void* d_out, int out_size) {
    const float* A      = (const float*)d_in[0];
    const int*   qw     = (const int*)  d_in[1];
    const float* scales = (const float*)d_in[2];
    const float* zeros  = (const float*)d_in[3];
    const float* bias   = (const float*)d_in[4];
    float*       out    = (float*)d_out;

    void *pA16 = nullptr, *pW16 = nullptr;
    cudaGetSymbolAddress(&pA16, g_A16);
    cudaGetSymbolAddress(&pW16, g_W16);
    __half* A16 = (__half*)pA16;
    __half* W16 = (__half*)pW16;

    pass1_kernel<<<NBLK_A + NBLK_W, 256>>>(A, qw, scales, zeros, A16, W16);

    PFN_encodeTiled enc = nullptr;
    cudaDriverEntryPointQueryResult qres;
    cudaGetDriverEntryPointByVersion("cuTensorMapEncodeTiled", (void**)&enc,
                                     12000, cudaEnableDefault, &qres);
    if (!enc) return;

    CUtensorMap tmA, tmB;
    {
        cuuint64_t dims[2]    = {(cuuint64_t)Kdim, (cuuint64_t)Mdim};
        cuuint64_t strides[1] = {(cuuint64_t)Kdim * 2};
        cuuint32_t box[2]     = {TILE_K, TILE_M};  // {64, 128}
        cuuint32_t es[2]      = {1, 1};
        enc(&tmA, CU_TENSOR_MAP_DATA_TYPE_FLOAT16, 2, A16, dims, strides, box, es,
            CU_TENSOR_MAP_INTERLEAVE_NONE, CU_TENSOR_MAP_SWIZZLE_128B,
            CU_TENSOR_MAP_L2_PROMOTION_L2_128B, CU_TENSOR_MAP_FLOAT_OOB_FILL_NONE);
    }
    {
        cuuint64_t dims[2]    = {(cuuint64_t)Kdim, (cuuint64_t)Ndim};
        cuuint64_t strides[1] = {(cuuint64_t)Kdim * 2};
        cuuint32_t box[2]     = {TILE_K, TILE_N};  // {64, 64}
        cuuint32_t es[2]      = {1, 1};
        enc(&tmB, CU_TENSOR_MAP_DATA_TYPE_FLOAT16, 2, W16, dims, strides, box, es,
            CU_TENSOR_MAP_INTERLEAVE_NONE, CU_TENSOR_MAP_SWIZZLE_128B,
            CU_TENSOR_MAP_L2_PROMOTION_L2_128B, CU_TENSOR_MAP_FLOAT_OOB_FILL_NONE);
    }

    cudaFuncSetAttribute(gemm_f16_kernel,
                         cudaFuncAttributeMaxDynamicSharedMemorySize, SMEM_TOTAL);
    dim3 grid(Ndim / TILE_N, Mdim / TILE_M);  // (64, 16) = 1024 tiles
    gemm_f16_kernel<<<grid, 128, SMEM_TOTAL>>>(tmA, tmB, bias, out);
}

// round 15
// speedup vs baseline: 1.8138x; 1.0478x over previous
#include <cuda_runtime.h>
#include <cuda.h>
#include <cuda_fp16.h>
#include <cstdint>

// ============================================================================
// out[m,n] = sum_k A[m,k] * (q[n,k]-zeros[n,k/128])*scales[n,k/128] + bias[n]
// M=2048, K=4096, N=4096, G=32.
// Pass 1 (R12-validated, 16 elem/thread): A fp32->fp16, W dequant->fp16.
// Pass 2: fp16 GEMM, TILE 128x64, 128 thr / 4 warps, 4 CTAs/SM, 2-stage TMA.
// R15: cluster-2 pairs (same bm, adjacent bn) share the A tile via TMA
// MULTICAST -> smem-fill traffic 1536->1024MB. Evidence: GEMM measured at
// ~6270 B/cyc == the 6300 B/cyc LTS cap (L2-bound; tensor 82% is a symptom).
// Backpressure: per-stage afree mbarrier (count 2) in rank0's smem.
// ============================================================================

static constexpr int Mdim = 2048, Kdim = 4096, Ndim = 4096, Gdim = 32;

static constexpr int TILE_M = 128, TILE_N = 64, TILE_K = 64;
static constexpr int STAGES = 2;
static constexpr int A_STAGE_BYTES = TILE_M * TILE_K * 2;  // 16384
static constexpr int B_STAGE_BYTES = TILE_N * TILE_K * 2;  // 8192
static constexpr int STAGE_BYTES = A_STAGE_BYTES + B_STAGE_BYTES;  // 24576
static constexpr int OFF_FULL  = 0;    // 2 x 8B
static constexpr int OFF_AFREE = 16;   // 2 x 8B (A-region free, count 2)
static constexpr int OFF_STAGE = 1024; // 1024-aligned for SW128
static constexpr int SMEM_TOTAL = OFF_STAGE + STAGES * STAGE_BYTES;  // 50176
static constexpr int NUM_SLABS = Kdim / TILE_K;  // 64

static __device__ __align__(1024) __half g_A16[(size_t)Mdim * Kdim];
static __device__ __align__(1024) __half g_W16[(size_t)Ndim * Kdim];

#define DEVINL __device__ __forceinline__

DEVINL uint32_t smem_u32(const void* p) {
    uint32_t a;
    asm("{ .reg .u64 t; cvta.to.shared.u64 t, %1; cvt.u32.u64 %0, t; }"
        : "=r"(a) : "l"(p));
    return a;
}
DEVINL uint32_t cluster_rank() {
    uint32_t r;
    asm("mov.u32 %0, %%cluster_ctarank;" : "=r"(r));
    return r;
}
DEVINL void cluster_sync() {
    asm volatile("barrier.cluster.arrive.aligned;" ::: "memory");
    asm volatile("barrier.cluster.wait.aligned;" ::: "memory");
}
DEVINL void mbar_init(uint32_t a, uint32_t cnt) {
    asm volatile("mbarrier.init.shared.b64 [%0], %1;" :: "r"(a), "r"(cnt) : "memory");
}
DEVINL void mbar_expect_tx(uint32_t a, uint32_t bytes) {
    asm volatile("mbarrier.arrive.expect_tx.shared.b64 _, [%0], %1;"
                 :: "r"(a), "r"(bytes) : "memory");
}
DEVINL void mbar_arrive_local(uint32_t a) {
    asm volatile("mbarrier.arrive.shared.b64 _, [%0];" :: "r"(a) : "memory");
}
// arrive on the same-offset mbarrier in cluster CTA `rank` (release.cluster)
DEVINL void mbar_arrive_cluster(uint32_t a, uint32_t rank) {
    asm volatile(
        "{\n\t.reg .b32 ra;\n\t"
        "mapa.shared::cluster.u32 ra, %0, %1;\n\t"
        "mbarrier.arrive.shared::cluster.b64 _, [ra];\n\t"
        "}" :: "r"(a), "r"(rank) : "memory");
}
DEVINL void mbar_wait(uint32_t a, uint32_t parity) {
    asm volatile(
        "{\n\t.reg .pred P;\n\t"
        "LAB_%=:\n\t"
        "mbarrier.try_wait.parity.acquire.cta.shared::cta.b64 P, [%0], %1, 0x989680;\n\t"
        "@!P bra LAB_%=;\n\t"
        "}" :: "r"(a), "r"(parity) : "memory");
}
// cluster-scope acquire (observes release-arrives from the peer CTA)
DEVINL void mbar_wait_cluster(uint32_t a, uint32_t parity) {
    asm volatile(
        "{\n\t.reg .pred P;\n\t"
        "LAB_%=:\n\t"
        "mbarrier.try_wait.parity.acquire.cluster.shared::cta.b64 P, [%0], %1, 0x989680;\n\t"
        "@!P bra LAB_%=;\n\t"
        "}" :: "r"(a), "r"(parity) : "memory");
}
DEVINL void tma_2d(uint32_t smem, const void* map, int x, int y, uint32_t bar) {
    asm volatile(
        "cp.async.bulk.tensor.2d.shared::cta.global.tile.mbarrier::complete_tx::bytes "
        "[%0], [%1, {%2, %3}], [%4];"
        :: "r"(smem), "l"(map), "r"(x), "r"(y), "r"(bar) : "memory");
}
// multicast: data + complete_tx delivered at SAME smem offsets in every CTA
// whose bit is set in mask (each CTA's own barrier at that offset).
DEVINL void tma_2d_mcast(uint32_t smem, const void* map, int x, int y,
                         uint32_t bar, uint16_t mask) {
    asm volatile(
        "cp.async.bulk.tensor.2d.shared::cluster.global.tile"
        ".mbarrier::complete_tx::bytes.multicast::cluster "
        "[%0], [%1, {%2, %3}], [%4], %5;"
        :: "r"(smem), "l"(map), "r"(x), "r"(y), "r"(bar), "h"(mask) : "memory");
}
DEVINL void fence_proxy_async() {
    asm volatile("fence.proxy.async.shared::cta;" ::: "memory");
}
DEVINL void ldsm_x4(uint32_t& r0, uint32_t& r1, uint32_t& r2, uint32_t& r3,
                    uint32_t addr) {
    asm volatile("ldmatrix.sync.aligned.m8n8.x4.shared.b16 {%0,%1,%2,%3}, [%4];"
                 : "=r"(r0), "=r"(r1), "=r"(r2), "=r"(r3) : "r"(addr));
}
DEVINL void mma16816(float* c, const uint32_t* a, uint32_t b0, uint32_t b1) {
    asm volatile(
        "mma.sync.aligned.m16n8k16.row.col.f32.f16.f16.f32 "
        "{%0,%1,%2,%3}, {%4,%5,%6,%7}, {%8,%9}, {%0,%1,%2,%3};"
        : "+f"(c[0]), "+f"(c[1]), "+f"(c[2]), "+f"(c[3])
        : "r"(a[0]), "r"(a[1]), "r"(a[2]), "r"(a[3]), "r"(b0), "r"(b1));
}

// ---------------------------- Pass 1 (R12-validated) ------------------------
static constexpr int NBLK_A = (Mdim * Kdim / 16) / 256;  // 2048
static constexpr int NBLK_W = (Ndim * Kdim / 16) / 256;  // 4096

__global__ void __launch_bounds__(256) pass1_kernel(
    const float* __restrict__ A, const int* __restrict__ q,
    const float* __restrict__ sc, const float* __restrict__ zr,
    __half* __restrict__ A16, __half* __restrict__ W16) {
    int bid = blockIdx.x;
    if (bid < NBLK_A) {
        int t = bid * 256 + threadIdx.x;
        const float4* a4 = reinterpret_cast<const float4*>(A) + (size_t)t * 4;
        float4 v[4];
        #pragma unroll
        for (int i = 0; i < 4; i++) v[i] = a4[i];  // 4 LDG.128 in flight
        #pragma unroll
        for (int i = 0; i < 4; i += 2) {
            __half2 h[4];
            h[0] = __floats2half2_rn(v[i].x, v[i].y);
            h[1] = __floats2half2_rn(v[i].z, v[i].w);
            h[2] = __floats2half2_rn(v[i + 1].x, v[i + 1].y);
            h[3] = __floats2half2_rn(v[i + 1].z, v[i + 1].w);
            reinterpret_cast<uint4*>(A16)[(size_t)t * 2 + (i >> 1)] =
                *reinterpret_cast<uint4*>(h);
        }
    } else {
        int t = (bid - NBLK_A) * 256 + threadIdx.x;
        int k16 = t & (Kdim / 16 - 1);
        int n = t >> 8;
        int g = k16 >> 3;
        float s = sc[n * Gdim + g];
        float z = zr[n * Gdim + g];
        const int4* qp = reinterpret_cast<const int4*>(q) + (size_t)t * 4;
        int4 v[4];
        #pragma unroll
        for (int i = 0; i < 4; i++) v[i] = qp[i];
        #pragma unroll
        for (int i = 0; i < 4; i += 2) {
            __half2 h[4];
            h[0] = __floats2half2_rn(((float)v[i].x - z) * s, ((float)v[i].y - z) * s);
            h[1] = __floats2half2_rn(((float)v[i].z - z) * s, ((float)v[i].w - z) * s);
            h[2] = __floats2half2_rn(((float)v[i+1].x - z) * s, ((float)v[i+1].y - z) * s);
            h[3] = __floats2half2_rn(((float)v[i+1].w - z) * s, ((float)v[i+1].w - z) * s);
            // NOTE: h[3] line fixed below (z/w lanes) — see corrected body
            h[3] = __floats2half2_rn(((float)v[i+1].z - z) * s, ((float)v[i+1].w - z) * s);
            reinterpret_cast<uint4*>(W16)[(size_t)t * 2 + (i >> 1)] =
                *reinterpret_cast<uint4*>(h);
        }
    }
}

// ---------------------------- Pass 2: GEMM + A-multicast --------------------
__global__ void __launch_bounds__(128, 4) __cluster_dims__(2, 1, 1)
gemm_f16_kernel(const __grid_constant__ CUtensorMap tmA,
                const __grid_constant__ CUtensorMap tmB,
                const float* __restrict__ bias,
                float* __restrict__ out) {
    extern __shared__ char smem[];
    uint32_t sb = smem_u32(smem);
    int tid = threadIdx.x, wid = tid >> 5, lane = tid & 31;
    int bn = blockIdx.x, bm = blockIdx.y;
    uint32_t rank = cluster_rank();    // pair = (bm, 2j) , (bm, 2j+1)
    int wm = wid >> 1, wn = wid & 1;   // warp coords: 2(M) x 2(N)

    if (tid == 0) {
        #pragma unroll
        for (int i = 0; i < STAGES; i++) {
            mbar_init(sb + OFF_FULL + i * 8, 1);
            mbar_init(sb + OFF_AFREE + i * 8, 2);  // both CTAs consumed
        }
        fence_proxy_async();
    }
    __syncthreads();
    // local expects BEFORE cluster sync so no complete_tx can precede them
    if (tid == 0) {
        mbar_expect_tx(sb + OFF_FULL + 0, STAGE_BYTES);
        mbar_expect_tx(sb + OFF_FULL + 8, STAGE_BYTES);
    }
    cluster_sync();   // inits + expects visible cluster-wide

    // Prologue: rank0 multicasts A (serves both CTAs); each CTA loads own B.
    if (tid == 0) {
        #pragma unroll
        for (int j = 0; j < STAGES; j++) {
            uint32_t fullb = sb + OFF_FULL + j * 8;
            uint32_t sA = sb + OFF_STAGE + j * STAGE_BYTES;
            if (rank == 0)
                tma_2d_mcast(sA, &tmA, j * TILE_K, bm * TILE_M, fullb, 0x3);
            tma_2d(sA + A_STAGE_BYTES, &tmB, j * TILE_K, bn * TILE_N, fullb);
        }
    }

    // ldmatrix address components (SW128: xor = (lane&7)*16)
    int a_row = wm * 64 + (lane & 15);
    int a_khalf = (lane & 16);
    int b_row = wn * 32 + ((lane & 16) >> 1) + (lane & 7);
    int b_khalf = (lane & 8) << 1;
    int sw_xor = (lane & 7) * 16;

    uint32_t aRowOff[4], bRowOff[2];
    #pragma unroll
    for (int mb = 0; mb < 4; mb++) aRowOff[mb] = (uint32_t)(a_row + mb * 16) * 128;
    #pragma unroll
    for (int j = 0; j < 2; j++)
        bRowOff[j] = A_STAGE_BYTES + (uint32_t)(b_row + j * 16) * 128;

    float acc[4][4][4];
    #pragma unroll
    for (int mb = 0; mb < 4; mb++)
        #pragma unroll
        for (int nb = 0; nb < 4; nb++)
            #pragma unroll
            for (int i = 0; i < 4; i++) acc[mb][nb][i] = 0.0f;

    for (int s = 0; s < NUM_SLABS; s++) {
        int st = s & 1;
        int ph = (s >> 1) & 1;
        mbar_wait(sb + OFF_FULL + st * 8, ph);
        uint32_t base = sb + OFF_STAGE + st * STAGE_BYTES;

        #pragma unroll
        for (int ks = 0; ks < 4; ks++) {
            int koffA = ((ks * 32) | a_khalf) ^ sw_xor;
            int koffB = ((ks * 32) | b_khalf) ^ sw_xor;
            uint32_t a[4][4], b[2][4];
            #pragma unroll
            for (int mb = 0; mb < 4; mb++)
                ldsm_x4(a[mb][0], a[mb][1], a[mb][2], a[mb][3],
                        base + aRowOff[mb] + koffA);
            #pragma unroll
            for (int j = 0; j < 2; j++)
                ldsm_x4(b[j][0], b[j][1], b[j][2], b[j][3],
                        base + bRowOff[j] + koffB);
            #pragma unroll
            for (int mb = 0; mb < 4; mb++) {
                #pragma unroll
                for (int nb = 0; nb < 4; nb++) {
                    int j = nb >> 1, h = (nb & 1) * 2;
                    mma16816(acc[mb][nb], a[mb], b[j][h], b[j][h + 1]);
                }
            }
        }

        __syncthreads();                       // stage st consumed (this CTA)
        if (tid == 0) {
            bool refill = (s + STAGES < NUM_SLABS);
            if (refill)                        // own expect BEFORE afree arrive
                mbar_expect_tx(sb + OFF_FULL + st * 8, STAGE_BYTES);
            // signal A-region free to rank0 (release)
            if (rank == 0) mbar_arrive_local(sb + OFF_AFREE + st * 8);
            else           mbar_arrive_cluster(sb + OFF_AFREE + st * 8, 0);
            if (refill) {
                uint32_t fullb = sb + OFF_FULL + st * 8;
                uint32_t base2 = sb + OFF_STAGE + st * STAGE_BYTES;
                if (rank == 0) {
                    // wait until BOTH CTAs freed the stage, then multicast A
                    mbar_wait_cluster(sb + OFF_AFREE + st * 8, ph);
                    tma_2d_mcast(base2, &tmA, (s + STAGES) * TILE_K,
                                 bm * TILE_M, fullb, 0x3);
                }
                tma_2d(base2 + A_STAGE_BYTES, &tmB, (s + STAGES) * TILE_K,
                       bn * TILE_N, fullb);
            }
        }
    }

    // ---------------- epilogue ----------------
    int gr = lane >> 2, gc = (lane & 3) * 2;
    #pragma unroll
    for (int mb = 0; mb < 4; mb++) {
        int row = bm * TILE_M + wm * 64 + mb * 16 + gr;
        float* orow0 = out + (size_t)row * Ndim;
        float* orow1 = out + (size_t)(row + 8) * Ndim;
        #pragma unroll
        for (int nb = 0; nb < 4; nb++) {
            int col = bn * TILE_N + wn * 32 + nb * 8 + gc;
            float2 bv = __ldg(reinterpret_cast<const float2*>(bias + col));
            float2 v0 = {acc[mb][nb][0] + bv.x, acc[mb][nb][1] + bv.y};
            float2 v1 = {acc[mb][nb][2] + bv.x, acc[mb][nb][3] + bv.y};
            *reinterpret_cast<float2*>(orow0 + col) = v0;
            *reinterpret_cast<float2*>(orow1 + col) = v1;
        }
    }
    cluster_sync();  // no CTA exits while peer multicasts could be in flight
}

// ---------------------------- host launch -----------------------------------
typedef CUresult (*PFN_encodeTiled)(
    CUtensorMap*, CUtensorMapDataType, cuuint32_t, void*,
    const cuuint64_t*, const cuuint64_t*, const cuuint32_t*, const cuuint32_t*,
    CUtensorMapInterleave, CUtensorMapSwizzle, CUtensorMapL2promotion,
    CUtensorMapFloatOOBfill);

extern "C" void kernel_launch(void* const* d_in, const int* in_sizes, int n_in,
                              void* d_out, int out_size) {
    const float* A      = (const float*)d_in[0];
    const int*   qw     = (const int*)  d_in[1];
    const float* scales = (const float*)d_in[2];
    const float* zeros  = (const float*)d_in[3];
    const float* bias   = (const float*)d_in[4];
    float*       out    = (float*)d_out;

    void *pA16 = nullptr, *pW16 = nullptr;
    cudaGetSymbolAddress(&pA16, g_A16);
    cudaGetSymbolAddress(&pW16, g_W16);
    __half* A16 = (__half*)pA16;
    __half* W16 = (__half*)pW16;

    pass1_kernel<<<NBLK_A + NBLK_W, 256>>>(A, qw, scales, zeros, A16, W16);

    PFN_encodeTiled enc = nullptr;
    cudaDriverEntryPointQueryResult qres;
    cudaGetDriverEntryPointByVersion("cuTensorMapEncodeTiled", (void**)&enc,
                                     12000, cudaEnableDefault, &qres);
    if (!enc) return;

    CUtensorMap tmA, tmB;
    {
        cuuint64_t dims[2]    = {(cuuint64_t)Kdim, (cuuint64_t)Mdim};
        cuuint64_t strides[1] = {(cuuint64_t)Kdim * 2};
        cuuint32_t box[2]     = {TILE_K, TILE_M};  // {64, 128}
        cuuint32_t es[2]      = {1, 1};
        enc(&tmA, CU_TENSOR_MAP_DATA_TYPE_FLOAT16, 2, A16, dims, strides, box, es,
            CU_TENSOR_MAP_INTERLEAVE_NONE, CU_TENSOR_MAP_SWIZZLE_128B,
            CU_TENSOR_MAP_L2_PROMOTION_L2_128B, CU_TENSOR_MAP_FLOAT_OOB_FILL_NONE);
    }
    {
        cuuint64_t dims[2]    = {(cuuint64_t)Kdim, (cuuint64_t)Ndim};
        cuuint64_t strides[1] = {(cuuint64_t)Kdim * 2};
        cuuint32_t box[2]     = {TILE_K, TILE_N};  // {64, 64}
        cuuint32_t es[2]      = {1, 1};
        enc(&tmB, CU_TENSOR_MAP_DATA_TYPE_FLOAT16, 2, W16, dims, strides, box, es,
            CU_TENSOR_MAP_INTERLEAVE_NONE, CU_TENSOR_MAP_SWIZZLE_128B,
            CU_TENSOR_MAP_L2_PROMOTION_L2_128B, CU_TENSOR_MAP_FLOAT_OOB_FILL_NONE);
    }

    cudaFuncSetAttribute(gemm_f16_kernel,
                         cudaFuncAttributeMaxDynamicSharedMemorySize, SMEM_TOTAL);
    dim3 grid(Ndim / TILE_N, Mdim / TILE_M);  // (64, 16); clusters pair x-adjacent
    gemm_f16_kernel<<<grid, 128, SMEM_TOTAL>>>(tmA, tmB, bias, out);
}

// round 16
// speedup vs baseline: 1.8644x; 1.0279x over previous
#include <cuda_runtime.h>
#include <cuda.h>
#include <cuda_fp16.h>
#include <cstdint>

// ============================================================================
// out[m,n] = sum_k A[m,k] * (q[n,k]-zeros[n,k/128])*scales[n,k/128] + bias[n]
// M=2048, K=4096, N=4096, G=32.
// R16 = R12 (validated best, 162.3us) + bias->smem preload (zero-risk).
// Evidence trail: tensor-busy invariant 114us (HMMA issue floor); slot
// quantization ceiling 86.5% at 1024 tiles/592 slots; R12 sits at 82% --
// within ~6us of the floor. R13 (fusion) and R15 (multicast) both falsified;
// reverting to the validated configuration.
// GEMM: fp16 mma.sync.m16n8k16, TILE 128x64, 128 thr / 4 warps (2x2),
// warp tile 64x32, 4 CTAs/SM, 2-stage TMA, static (64,16) grid.
// Pass 1: fused A-convert + W-dequant, 16 elems/thread (R12-validated).
// ============================================================================

static constexpr int Mdim = 2048, Kdim = 4096, Ndim = 4096, Gdim = 32;

static constexpr int TILE_M = 128, TILE_N = 64, TILE_K = 64;
static constexpr int STAGES = 2;
static constexpr int A_STAGE_BYTES = TILE_M * TILE_K * 2;  // 16384
static constexpr int B_STAGE_BYTES = TILE_N * TILE_K * 2;  // 8192
static constexpr int STAGE_BYTES = A_STAGE_BYTES + B_STAGE_BYTES;  // 24576
static constexpr int OFF_FULL  = 0;    // 2 x 8B
static constexpr int OFF_BIAS  = 256;  // 64 floats = 256B
static constexpr int OFF_STAGE = 1024; // 1024-aligned for SW128
static constexpr int SMEM_TOTAL = OFF_STAGE + STAGES * STAGE_BYTES;  // 50176
static constexpr int NUM_SLABS = Kdim / TILE_K;  // 64

static __device__ __align__(1024) __half g_A16[(size_t)Mdim * Kdim];
static __device__ __align__(1024) __half g_W16[(size_t)Ndim * Kdim];

#define DEVINL __device__ __forceinline__

DEVINL uint32_t smem_u32(const void* p) {
    uint32_t a;
    asm("{ .reg .u64 t; cvta.to.shared.u64 t, %1; cvt.u32.u64 %0, t; }"
        : "=r"(a) : "l"(p));
    return a;
}
DEVINL void mbar_init(uint32_t a, uint32_t cnt) {
    asm volatile("mbarrier.init.shared.b64 [%0], %1;" :: "r"(a), "r"(cnt) : "memory");
}
DEVINL void mbar_expect_tx(uint32_t a, uint32_t bytes) {
    asm volatile("mbarrier.arrive.expect_tx.shared.b64 _, [%0], %1;"
                 :: "r"(a), "r"(bytes) : "memory");
}
DEVINL void mbar_wait(uint32_t a, uint32_t parity) {
    asm volatile(
        "{\n\t.reg .pred P;\n\t"
        "LAB_%=:\n\t"
        "mbarrier.try_wait.parity.acquire.cta.shared::cta.b64 P, [%0], %1, 0x989680;\n\t"
        "@!P bra LAB_%=;\n\t"
        "}" :: "r"(a), "r"(parity) : "memory");
}
DEVINL void tma_2d(uint32_t smem, const void* map, int x, int y, uint32_t bar) {
    asm volatile(
        "cp.async.bulk.tensor.2d.shared::cta.global.tile.mbarrier::complete_tx::bytes "
        "[%0], [%1, {%2, %3}], [%4];"
        :: "r"(smem), "l"(map), "r"(x), "r"(y), "r"(bar) : "memory");
}
DEVINL void fence_proxy_async() {
    asm volatile("fence.proxy.async.shared::cta;" ::: "memory");
}
DEVINL void ldsm_x4(uint32_t& r0, uint32_t& r1, uint32_t& r2, uint32_t& r3,
                    uint32_t addr) {
    asm volatile("ldmatrix.sync.aligned.m8n8.x4.shared.b16 {%0,%1,%2,%3}, [%4];"
                 : "=r"(r0), "=r"(r1), "=r"(r2), "=r"(r3) : "r"(addr));
}
DEVINL void mma16816(float* c, const uint32_t* a, uint32_t b0, uint32_t b1) {
    asm volatile(
        "mma.sync.aligned.m16n8k16.row.col.f32.f16.f16.f32 "
        "{%0,%1,%2,%3}, {%4,%5,%6,%7}, {%8,%9}, {%0,%1,%2,%3};"
        : "+f"(c[0]), "+f"(c[1]), "+f"(c[2]), "+f"(c[3])
        : "r"(a[0]), "r"(a[1]), "r"(a[2]), "r"(a[3]), "r"(b0), "r"(b1));
}

// ---------------------------- Pass 1: fused, 16 elems/thread ----------------
static constexpr int NBLK_A = (Mdim * Kdim / 16) / 256;  // 2048
static constexpr int NBLK_W = (Ndim * Kdim / 16) / 256;  // 4096

__global__ void __launch_bounds__(256) pass1_kernel(
    const float* __restrict__ A, const int* __restrict__ q,
    const float* __restrict__ sc, const float* __restrict__ zr,
    __half* __restrict__ A16, __half* __restrict__ W16) {
    int bid = blockIdx.x;
    if (bid < NBLK_A) {
        int t = bid * 256 + threadIdx.x;
        const float4* a4 = reinterpret_cast<const float4*>(A) + (size_t)t * 4;
        float4 v[4];
        #pragma unroll
        for (int i = 0; i < 4; i++) v[i] = a4[i];  // 4 LDG.128 in flight
        #pragma unroll
        for (int i = 0; i < 4; i += 2) {
            __half2 h[4];
            h[0] = __floats2half2_rn(v[i].x, v[i].y);
            h[1] = __floats2half2_rn(v[i].z, v[i].w);
            h[2] = __floats2half2_rn(v[i + 1].x, v[i + 1].y);
            h[3] = __floats2half2_rn(v[i + 1].z, v[i + 1].w);
            reinterpret_cast<uint4*>(A16)[(size_t)t * 2 + (i >> 1)] =
                *reinterpret_cast<uint4*>(h);
        }
    } else {
        int t = (bid - NBLK_A) * 256 + threadIdx.x;
        int k16 = t & (Kdim / 16 - 1);   // 256 chunks of 16 per row
        int n = t >> 8;
        int g = k16 >> 3;                // 8 chunks of 16 per group of 128
        float s = sc[n * Gdim + g];
        float z = zr[n * Gdim + g];
        const int4* qp = reinterpret_cast<const int4*>(q) + (size_t)t * 4;
        int4 v[4];
        #pragma unroll
        for (int i = 0; i < 4; i++) v[i] = qp[i];
        #pragma unroll
        for (int i = 0; i < 4; i += 2) {
            __half2 h[4];
            h[0] = __floats2half2_rn(((float)v[i].x - z) * s, ((float)v[i].y - z) * s);
            h[1] = __floats2half2_rn(((float)v[i].z - z) * s, ((float)v[i].w - z) * s);
            h[2] = __floats2half2_rn(((float)v[i+1].x - z) * s, ((float)v[i+1].y - z) * s);
            h[3] = __floats2half2_rn(((float)v[i+1].z - z) * s, ((float)v[i+1].w - z) * s);
            reinterpret_cast<uint4*>(W16)[(size_t)t * 2 + (i >> 1)] =
                *reinterpret_cast<uint4*>(h);
        }
    }
}

// ---------------------------- Pass 2: GEMM (R12 + smem bias) ----------------
__global__ void __launch_bounds__(128, 4)
gemm_f16_kernel(const __grid_constant__ CUtensorMap tmA,
                const __grid_constant__ CUtensorMap tmB,
                const float* __restrict__ bias,
                float* __restrict__ out) {
    extern __shared__ char smem[];
    uint32_t sb = smem_u32(smem);
    int tid = threadIdx.x, wid = tid >> 5, lane = tid & 31;
    int bn = blockIdx.x, bm = blockIdx.y;
    int wm = wid >> 1, wn = wid & 1;  // warp coords: 2(M) x 2(N)

    if (tid == 0) {
        #pragma unroll
        for (int i = 0; i < STAGES; i++) mbar_init(sb + OFF_FULL + i * 8, 1);
        fence_proxy_async();
    }
    // preload the tile's 64 bias values into smem (read in epilogue via LDS)
    if (tid < 64)
        reinterpret_cast<float*>(smem + OFF_BIAS)[tid] = bias[bn * TILE_N + tid];
    __syncthreads();

    // Prologue: fill both stages
    if (tid == 0) {
        #pragma unroll
        for (int j = 0; j < STAGES; j++) {
            uint32_t fullb = sb + OFF_FULL + j * 8;
            uint32_t sA = sb + OFF_STAGE + j * STAGE_BYTES;
            mbar_expect_tx(fullb, STAGE_BYTES);
            tma_2d(sA, &tmA, j * TILE_K, bm * TILE_M, fullb);
            tma_2d(sA + A_STAGE_BYTES, &tmB, j * TILE_K, bn * TILE_N, fullb);
        }
    }

    // ldmatrix address components (SW128: xor = (lane&7)*16)
    int a_row = wm * 64 + (lane & 15);                      // + mb*16, <=127
    int a_khalf = (lane & 16);
    int b_row = wn * 32 + ((lane & 16) >> 1) + (lane & 7);  // + j*16, <=63
    int b_khalf = (lane & 8) << 1;
    int sw_xor = (lane & 7) * 16;

    uint32_t aRowOff[4], bRowOff[2];
    #pragma unroll
    for (int mb = 0; mb < 4; mb++) aRowOff[mb] = (uint32_t)(a_row + mb * 16) * 128;
    #pragma unroll
    for (int j = 0; j < 2; j++)
        bRowOff[j] = A_STAGE_BYTES + (uint32_t)(b_row + j * 16) * 128;

    float acc[4][4][4];
    #pragma unroll
    for (int mb = 0; mb < 4; mb++)
        #pragma unroll
        for (int nb = 0; nb < 4; nb++)
            #pragma unroll
            for (int i = 0; i < 4; i++) acc[mb][nb][i] = 0.0f;

    for (int s = 0; s < NUM_SLABS; s++) {
        int st = s & 1;
        int ph = (s >> 1) & 1;
        mbar_wait(sb + OFF_FULL + st * 8, ph);
        uint32_t base = sb + OFF_STAGE + st * STAGE_BYTES;

        #pragma unroll
        for (int ks = 0; ks < 4; ks++) {
            int koffA = ((ks * 32) | a_khalf) ^ sw_xor;
            int koffB = ((ks * 32) | b_khalf) ^ sw_xor;
            uint32_t a[4][4], b[2][4];
            #pragma unroll
            for (int mb = 0; mb < 4; mb++)
                ldsm_x4(a[mb][0], a[mb][1], a[mb][2], a[mb][3],
                        base + aRowOff[mb] + koffA);
            #pragma unroll
            for (int j = 0; j < 2; j++)
                ldsm_x4(b[j][0], b[j][1], b[j][2], b[j][3],
                        base + bRowOff[j] + koffB);
            #pragma unroll
            for (int mb = 0; mb < 4; mb++) {
                #pragma unroll
                for (int nb = 0; nb < 4; nb++) {
                    int j = nb >> 1, h = (nb & 1) * 2;
                    mma16816(acc[mb][nb], a[mb], b[j][h], b[j][h + 1]);
                }
            }
        }

        // stage fully consumed -> one barrier, tid0 refills for slab s+2
        __syncthreads();
        if (tid == 0 && s + STAGES < NUM_SLABS) {
            uint32_t fullb = sb + OFF_FULL + st * 8;
            mbar_expect_tx(fullb, STAGE_BYTES);
            tma_2d(base, &tmA, (s + STAGES) * TILE_K, bm * TILE_M, fullb);
            tma_2d(base + A_STAGE_BYTES, &tmB, (s + STAGES) * TILE_K,
                   bn * TILE_N, fullb);
        }
    }

    // ---------------- epilogue (bias from smem) ----------------
    const float* sbias = reinterpret_cast<const float*>(smem + OFF_BIAS);
    int gr = lane >> 2, gc = (lane & 3) * 2;
    #pragma unroll
    for (int mb = 0; mb < 4; mb++) {
        int row = bm * TILE_M + wm * 64 + mb * 16 + gr;
        float* orow0 = out + (size_t)row * Ndim;
        float* orow1 = out + (size_t)(row + 8) * Ndim;
        #pragma unroll
        for (int nb = 0; nb < 4; nb++) {
            int lc = wn * 32 + nb * 8 + gc;
            int col = bn * TILE_N + lc;
            float bx = sbias[lc], by = sbias[lc + 1];
            float2 v0 = {acc[mb][nb][0] + bx, acc[mb][nb][1] + by};
            float2 v1 = {acc[mb][nb][2] + bx, acc[mb][nb][3] + by};
            *reinterpret_cast<float2*>(orow0 + col) = v0;
            *reinterpret_cast<float2*>(orow1 + col) = v1;
        }
    }
}

// ---------------------------- host launch -----------------------------------
typedef CUresult (*PFN_encodeTiled)(
    CUtensorMap*, CUtensorMapDataType, cuuint32_t, void*,
    const cuuint64_t*, const cuuint64_t*, const cuuint32_t*, const cuuint32_t*,
    CUtensorMapInterleave, CUtensorMapSwizzle, CUtensorMapL2promotion,
    CUtensorMapFloatOOBfill);

extern "C" void kernel_launch(void* const* d_in, const int* in_sizes, int n_in,
                              void* d_out, int out_size) {
    const float* A      = (const float*)d_in[0];
    const int*   qw     = (const int*)  d_in[1];
    const float* scales = (const float*)d_in[2];
    const float* zeros  = (const float*)d_in[3];
    const float* bias   = (const float*)d_in[4];
    float*       out    = (float*)d_out;

    void *pA16 = nullptr, *pW16 = nullptr;
    cudaGetSymbolAddress(&pA16, g_A16);
    cudaGetSymbolAddress(&pW16, g_W16);
    __half* A16 = (__half*)pA16;
    __half* W16 = (__half*)pW16;

    pass1_kernel<<<NBLK_A + NBLK_W, 256>>>(A, qw, scales, zeros, A16, W16);

    PFN_encodeTiled enc = nullptr;
    cudaDriverEntryPointQueryResult qres;
    cudaGetDriverEntryPointByVersion("cuTensorMapEncodeTiled", (void**)&enc,
                                     12000, cudaEnableDefault, &qres);
    if (!enc) return;

    CUtensorMap tmA, tmB;
    {
        cuuint64_t dims[2]    = {(cuuint64_t)Kdim, (cuuint64_t)Mdim};
        cuuint64_t strides[1] = {(cuuint64_t)Kdim * 2};
        cuuint32_t box[2]     = {TILE_K, TILE_M};  // {64, 128}
        cuuint32_t es[2]      = {1, 1};
        enc(&tmA, CU_TENSOR_MAP_DATA_TYPE_FLOAT16, 2, A16, dims, strides, box, es,
            CU_TENSOR_MAP_INTERLEAVE_NONE, CU_TENSOR_MAP_SWIZZLE_128B,
            CU_TENSOR_MAP_L2_PROMOTION_L2_128B, CU_TENSOR_MAP_FLOAT_OOB_FILL_NONE);
    }
    {
        cuuint64_t dims[2]    = {(cuuint64_t)Kdim, (cuuint64_t)Ndim};
        cuuint64_t strides[1] = {(cuuint64_t)Kdim * 2};
        cuuint32_t box[2]     = {TILE_K, TILE_N};  // {64, 64}
        cuuint32_t es[2]      = {1, 1};
        enc(&tmB, CU_TENSOR_MAP_DATA_TYPE_FLOAT16, 2, W16, dims, strides, box, es,
            CU_TENSOR_MAP_INTERLEAVE_NONE, CU_TENSOR_MAP_SWIZZLE_128B,
            CU_TENSOR_MAP_L2_PROMOTION_L2_128B, CU_TENSOR_MAP_FLOAT_OOB_FILL_NONE);
    }

    cudaFuncSetAttribute(gemm_f16_kernel,
                         cudaFuncAttributeMaxDynamicSharedMemorySize, SMEM_TOTAL);
    dim3 grid(Ndim / TILE_N, Mdim / TILE_M);  // (64, 16) = 1024 tiles
    gemm_f16_kernel<<<grid, 128, SMEM_TOTAL>>>(tmA, tmB, bias, out);
}

// round 17
// speedup vs baseline: 1.8680x; 1.0020x over previous
#include <cuda_runtime.h>
#include <cuda.h>
#include <cuda_fp16.h>
#include <cstdint>

// ============================================================================
// out[m,n] = sum_k A[m,k] * (q[n,k]-zeros[n,k/128])*scales[n,k/128] + bias[n]
// M=2048, K=4096, N=4096, G=32.
// R17 = R16 (validated R12 config + smem bias) + PDL: the GEMM launches
// programmatically-dependent on pass 1, runs its prologue (mbar init, bias
// fill, addressing) during pass-1's tail, and griddepcontrol.wait's (tid0,
// just before the first TMA) for pass-1 completion.
// Evidence: GEMM floor confirmed (~139-141us, tensor-busy 114us invariant);
// only the pass1->GEMM serialization seam (~2-4us) remains addressable.
// ============================================================================

static constexpr int Mdim = 2048, Kdim = 4096, Ndim = 4096, Gdim = 32;

static constexpr int TILE_M = 128, TILE_N = 64, TILE_K = 64;
static constexpr int STAGES = 2;
static constexpr int A_STAGE_BYTES = TILE_M * TILE_K * 2;  // 16384
static constexpr int B_STAGE_BYTES = TILE_N * TILE_K * 2;  // 8192
static constexpr int STAGE_BYTES = A_STAGE_BYTES + B_STAGE_BYTES;  // 24576
static constexpr int OFF_FULL  = 0;    // 2 x 8B
static constexpr int OFF_BIAS  = 256;  // 64 floats = 256B
static constexpr int OFF_STAGE = 1024; // 1024-aligned for SW128
static constexpr int SMEM_TOTAL = OFF_STAGE + STAGES * STAGE_BYTES;  // 50176
static constexpr int NUM_SLABS = Kdim / TILE_K;  // 64

static __device__ __align__(1024) __half g_A16[(size_t)Mdim * Kdim];
static __device__ __align__(1024) __half g_W16[(size_t)Ndim * Kdim];

#define DEVINL __device__ __forceinline__

DEVINL uint32_t smem_u32(const void* p) {
    uint32_t a;
    asm("{ .reg .u64 t; cvta.to.shared.u64 t, %1; cvt.u32.u64 %0, t; }"
        : "=r"(a) : "l"(p));
    return a;
}
DEVINL void mbar_init(uint32_t a, uint32_t cnt) {
    asm volatile("mbarrier.init.shared.b64 [%0], %1;" :: "r"(a), "r"(cnt) : "memory");
}
DEVINL void mbar_expect_tx(uint32_t a, uint32_t bytes) {
    asm volatile("mbarrier.arrive.expect_tx.shared.b64 _, [%0], %1;"
                 :: "r"(a), "r"(bytes) : "memory");
}
DEVINL void mbar_wait(uint32_t a, uint32_t parity) {
    asm volatile(
        "{\n\t.reg .pred P;\n\t"
        "LAB_%=:\n\t"
        "mbarrier.try_wait.parity.acquire.cta.shared::cta.b64 P, [%0], %1, 0x989680;\n\t"
        "@!P bra LAB_%=;\n\t"
        "}" :: "r"(a), "r"(parity) : "memory");
}
DEVINL void tma_2d(uint32_t smem, const void* map, int x, int y, uint32_t bar) {
    asm volatile(
        "cp.async.bulk.tensor.2d.shared::cta.global.tile.mbarrier::complete_tx::bytes "
        "[%0], [%1, {%2, %3}], [%4];"
        :: "r"(smem), "l"(map), "r"(x), "r"(y), "r"(bar) : "memory");
}
DEVINL void fence_proxy_async() {
    asm volatile("fence.proxy.async.shared::cta;" ::: "memory");
}
DEVINL void pdl_trigger() {   // allow dependents to launch early
    asm volatile("griddepcontrol.launch_dependents;" ::: "memory");
}
DEVINL void pdl_wait() {      // block until primary grid's writes are visible
    asm volatile("griddepcontrol.wait;" ::: "memory");
}
DEVINL void ldsm_x4(uint32_t& r0, uint32_t& r1, uint32_t& r2, uint32_t& r3,
                    uint32_t addr) {
    asm volatile("ldmatrix.sync.aligned.m8n8.x4.shared.b16 {%0,%1,%2,%3}, [%4];"
                 : "=r"(r0), "=r"(r1), "=r"(r2), "=r"(r3) : "r"(addr));
}
DEVINL void mma16816(float* c, const uint32_t* a, uint32_t b0, uint32_t b1) {
    asm volatile(
        "mma.sync.aligned.m16n8k16.row.col.f32.f16.f16.f32 "
        "{%0,%1,%2,%3}, {%4,%5,%6,%7}, {%8,%9}, {%0,%1,%2,%3};"
        : "+f"(c[0]), "+f"(c[1]), "+f"(c[2]), "+f"(c[3])
        : "r"(a[0]), "r"(a[1]), "r"(a[2]), "r"(a[3]), "r"(b0), "r"(b1));
}

// ---------------------------- Pass 1: fused, 16 elems/thread ----------------
static constexpr int NBLK_A = (Mdim * Kdim / 16) / 256;  // 2048
static constexpr int NBLK_W = (Ndim * Kdim / 16) / 256;  // 4096

__global__ void __launch_bounds__(256) pass1_kernel(
    const float* __restrict__ A, const int* __restrict__ q,
    const float* __restrict__ sc, const float* __restrict__ zr,
    __half* __restrict__ A16, __half* __restrict__ W16) {
    int bid = blockIdx.x;
    if (threadIdx.x == 0) pdl_trigger();  // let the GEMM start its prologue
    if (bid < NBLK_A) {
        int t = bid * 256 + threadIdx.x;
        const float4* a4 = reinterpret_cast<const float4*>(A) + (size_t)t * 4;
        float4 v[4];
        #pragma unroll
        for (int i = 0; i < 4; i++) v[i] = a4[i];  // 4 LDG.128 in flight
        #pragma unroll
        for (int i = 0; i < 4; i += 2) {
            __half2 h[4];
            h[0] = __floats2half2_rn(v[i].x, v[i].y);
            h[1] = __floats2half2_rn(v[i].z, v[i].w);
            h[2] = __floats2half2_rn(v[i + 1].x, v[i + 1].y);
            h[3] = __floats2half2_rn(v[i + 1].z, v[i + 1].w);
            reinterpret_cast<uint4*>(A16)[(size_t)t * 2 + (i >> 1)] =
                *reinterpret_cast<uint4*>(h);
        }
    } else {
        int t = (bid - NBLK_A) * 256 + threadIdx.x;
        int k16 = t & (Kdim / 16 - 1);   // 256 chunks of 16 per row
        int n = t >> 8;
        int g = k16 >> 3;                // 8 chunks of 16 per group of 128
        float s = sc[n * Gdim + g];
        float z = zr[n * Gdim + g];
        const int4* qp = reinterpret_cast<const int4*>(q) + (size_t)t * 4;
        int4 v[4];
        #pragma unroll
        for (int i = 0; i < 4; i++) v[i] = qp[i];
        #pragma unroll
        for (int i = 0; i < 4; i += 2) {
            __half2 h[4];
            h[0] = __floats2half2_rn(((float)v[i].x - z) * s, ((float)v[i].y - z) * s);
            h[1] = __floats2half2_rn(((float)v[i].z - z) * s, ((float)v[i].w - z) * s);
            h[2] = __floats2half2_rn(((float)v[i+1].x - z) * s, ((float)v[i+1].y - z) * s);
            h[3] = __floats2half2_rn(((float)v[i+1].z - z) * s, ((float)v[i+1].w - z) * s);
            reinterpret_cast<uint4*>(W16)[(size_t)t * 2 + (i >> 1)] =
                *reinterpret_cast<uint4*>(h);
        }
    }
}

// ---------------------------- Pass 2: GEMM (R16 + PDL wait) -----------------
__global__ void __launch_bounds__(128, 4)
gemm_f16_kernel(const __grid_constant__ CUtensorMap tmA,
                const __grid_constant__ CUtensorMap tmB,
                const float* __restrict__ bias,
                float* __restrict__ out) {
    extern __shared__ char smem[];
    uint32_t sb = smem_u32(smem);
    int tid = threadIdx.x, wid = tid >> 5, lane = tid & 31;
    int bn = blockIdx.x, bm = blockIdx.y;
    int wm = wid >> 1, wn = wid & 1;  // warp coords: 2(M) x 2(N)

    // ---- prologue work that does NOT touch pass-1 output (overlaps pass 1) -
    if (tid == 0) {
        #pragma unroll
        for (int i = 0; i < STAGES; i++) mbar_init(sb + OFF_FULL + i * 8, 1);
        fence_proxy_async();
    }
    if (tid < 64)   // bias is a kernel input, not a pass-1 product
        reinterpret_cast<float*>(smem + OFF_BIAS)[tid] = bias[bn * TILE_N + tid];
    __syncthreads();

    // ---- gate: pass-1 writes must be visible before TMA reads A16/W16 ------
    if (tid == 0) {
        pdl_wait();
        #pragma unroll
        for (int j = 0; j < STAGES; j++) {
            uint32_t fullb = sb + OFF_FULL + j * 8;
            uint32_t sA = sb + OFF_STAGE + j * STAGE_BYTES;
            mbar_expect_tx(fullb, STAGE_BYTES);
            tma_2d(sA, &tmA, j * TILE_K, bm * TILE_M, fullb);
            tma_2d(sA + A_STAGE_BYTES, &tmB, j * TILE_K, bn * TILE_N, fullb);
        }
    }

    // ldmatrix address components (SW128: xor = (lane&7)*16)
    int a_row = wm * 64 + (lane & 15);                      // + mb*16, <=127
    int a_khalf = (lane & 16);
    int b_row = wn * 32 + ((lane & 16) >> 1) + (lane & 7);  // + j*16, <=63
    int b_khalf = (lane & 8) << 1;
    int sw_xor = (lane & 7) * 16;

    uint32_t aRowOff[4], bRowOff[2];
    #pragma unroll
    for (int mb = 0; mb < 4; mb++) aRowOff[mb] = (uint32_t)(a_row + mb * 16) * 128;
    #pragma unroll
    for (int j = 0; j < 2; j++)
        bRowOff[j] = A_STAGE_BYTES + (uint32_t)(b_row + j * 16) * 128;

    float acc[4][4][4];
    #pragma unroll
    for (int mb = 0; mb < 4; mb++)
        #pragma unroll
        for (int nb = 0; nb < 4; nb++)
            #pragma unroll
            for (int i = 0; i < 4; i++) acc[mb][nb][i] = 0.0f;

    for (int s = 0; s < NUM_SLABS; s++) {
        int st = s & 1;
        int ph = (s >> 1) & 1;
        mbar_wait(sb + OFF_FULL + st * 8, ph);
        uint32_t base = sb + OFF_STAGE + st * STAGE_BYTES;

        #pragma unroll
        for (int ks = 0; ks < 4; ks++) {
            int koffA = ((ks * 32) | a_khalf) ^ sw_xor;
            int koffB = ((ks * 32) | b_khalf) ^ sw_xor;
            uint32_t a[4][4], b[2][4];
            #pragma unroll
            for (int mb = 0; mb < 4; mb++)
                ldsm_x4(a[mb][0], a[mb][1], a[mb][2], a[mb][3],
                        base + aRowOff[mb] + koffA);
            #pragma unroll
            for (int j = 0; j < 2; j++)
                ldsm_x4(b[j][0], b[j][1], b[j][2], b[j][3],
                        base + bRowOff[j] + koffB);
            #pragma unroll
            for (int mb = 0; mb < 4; mb++) {
                #pragma unroll
                for (int nb = 0; nb < 4; nb++) {
                    int j = nb >> 1, h = (nb & 1) * 2;
                    mma16816(acc[mb][nb], a[mb], b[j][h], b[j][h + 1]);
                }
            }
        }

        // stage fully consumed -> one barrier, tid0 refills for slab s+2
        __syncthreads();
        if (tid == 0 && s + STAGES < NUM_SLABS) {
            uint32_t fullb = sb + OFF_FULL + st * 8;
            mbar_expect_tx(fullb, STAGE_BYTES);
            tma_2d(base, &tmA, (s + STAGES) * TILE_K, bm * TILE_M, fullb);
            tma_2d(base + A_STAGE_BYTES, &tmB, (s + STAGES) * TILE_K,
                   bn * TILE_N, fullb);
        }
    }

    // ---------------- epilogue (bias from smem) ----------------
    const float* sbias = reinterpret_cast<const float*>(smem + OFF_BIAS);
    int gr = lane >> 2, gc = (lane & 3) * 2;
    #pragma unroll
    for (int mb = 0; mb < 4; mb++) {
        int row = bm * TILE_M + wm * 64 + mb * 16 + gr;
        float* orow0 = out + (size_t)row * Ndim;
        float* orow1 = out + (size_t)(row + 8) * Ndim;
        #pragma unroll
        for (int nb = 0; nb < 4; nb++) {
            int lc = wn * 32 + nb * 8 + gc;
            int col = bn * TILE_N + lc;
            float bx = sbias[lc], by = sbias[lc + 1];
            float2 v0 = {acc[mb][nb][0] + bx, acc[mb][nb][1] + by};
            float2 v1 = {acc[mb][nb][2] + bx, acc[mb][nb][3] + by};
            *reinterpret_cast<float2*>(orow0 + col) = v0;
            *reinterpret_cast<float2*>(orow1 + col) = v1;
        }
    }
}

// ---------------------------- host launch -----------------------------------
typedef CUresult (*PFN_encodeTiled)(
    CUtensorMap*, CUtensorMapDataType, cuuint32_t, void*,
    const cuuint64_t*, const cuuint64_t*, const cuuint32_t*, const cuuint32_t*,
    CUtensorMapInterleave, CUtensorMapSwizzle, CUtensorMapL2promotion,
    CUtensorMapFloatOOBfill);

extern "C" void kernel_launch(void* const* d_in, const int* in_sizes, int n_in,
                              void* d_out, int out_size) {
    const float* A      = (const float*)d_in[0];
    const int*   qw     = (const int*)  d_in[1];
    const float* scales = (const float*)d_in[2];
    const float* zeros  = (const float*)d_in[3];
    const float* bias   = (const float*)d_in[4];
    float*       out    = (float*)d_out;

    void *pA16 = nullptr, *pW16 = nullptr;
    cudaGetSymbolAddress(&pA16, g_A16);
    cudaGetSymbolAddress(&pW16, g_W16);
    __half* A16 = (__half*)pA16;
    __half* W16 = (__half*)pW16;

    pass1_kernel<<<NBLK_A + NBLK_W, 256>>>(A, qw, scales, zeros, A16, W16);

    PFN_encodeTiled enc = nullptr;
    cudaDriverEntryPointQueryResult qres;
    cudaGetDriverEntryPointByVersion("cuTensorMapEncodeTiled", (void**)&enc,
                                     12000, cudaEnableDefault, &qres);
    if (!enc) return;

    CUtensorMap tmA, tmB;
    {
        cuuint64_t dims[2]    = {(cuuint64_t)Kdim, (cuuint64_t)Mdim};
        cuuint64_t strides[1] = {(cuuint64_t)Kdim * 2};
        cuuint32_t box[2]     = {TILE_K, TILE_M};  // {64, 128}
        cuuint32_t es[2]      = {1, 1};
        enc(&tmA, CU_TENSOR_MAP_DATA_TYPE_FLOAT16, 2, A16, dims, strides, box, es,
            CU_TENSOR_MAP_INTERLEAVE_NONE, CU_TENSOR_MAP_SWIZZLE_128B,
            CU_TENSOR_MAP_L2_PROMOTION_L2_128B, CU_TENSOR_MAP_FLOAT_OOB_FILL_NONE);
    }
    {
        cuuint64_t dims[2]    = {(cuuint64_t)Kdim, (cuuint64_t)Ndim};
        cuuint64_t strides[1] = {(cuuint64_t)Kdim * 2};
        cuuint32_t box[2]     = {TILE_K, TILE_N};  // {64, 64}
        cuuint32_t es[2]      = {1, 1};
        enc(&tmB, CU_TENSOR_MAP_DATA_TYPE_FLOAT16, 2, W16, dims, strides, box, es,
            CU_TENSOR_MAP_INTERLEAVE_NONE, CU_TENSOR_MAP_SWIZZLE_128B,
            CU_TENSOR_MAP_L2_PROMOTION_L2_128B, CU_TENSOR_MAP_FLOAT_OOB_FILL_NONE);
    }

    cudaFuncSetAttribute(gemm_f16_kernel,
                         cudaFuncAttributeMaxDynamicSharedMemorySize, SMEM_TOTAL);

    // Launch the GEMM as a programmatic dependent of pass 1.
    cudaLaunchConfig_t cfg = {};
    cfg.gridDim = dim3(Ndim / TILE_N, Mdim / TILE_M);  // (64, 16)
    cfg.blockDim = dim3(128, 1, 1);
    cfg.dynamicSmemBytes = SMEM_TOTAL;
    cudaLaunchAttribute attrs[1];
    attrs[0].id = cudaLaunchAttributeProgrammaticStreamSerialization;
    attrs[0].val.programmaticStreamSerializationAllowed = 1;
    cfg.attrs = attrs;
    cfg.numAttrs = 1;
    cudaLaunchKernelEx(&cfg, gemm_f16_kernel, tmA, tmB, bias, out);
}